// round 3
// baseline (speedup 1.0000x reference)
#include <cuda_runtime.h>
#include <cuda_bf16.h>
#include <cstdint>

#define Bb 512
#define Tt 256
#define Ff 256
#define Hh 512
#define KTOT (Ff + Hh)          /* 768 */
#define G4 (4 * Hh)             /* 2048 */

#define BM 64
#define BU 32
#define KC 32
#define KP 40                   /* padded K stride in bf16 elems -> conflict-free LDS */
#define NCHUNK (Hh / KC)        /* 16 h-part K chunks */
#define CHUNK_ELEMS (4 * BU * KP)   /* 5120 bf16 per B chunk */

// dynamic smem layout (bf16 elems):
//   [0, 81920)        persistent B-hi (16 chunks x 5120)
//   [81920, 84480)    sAhi (64 x 40)
//   [84480, 87040)    sAlo
//   [87040, 92160)    sBlo (streamed chunk)
#define SM_BHI   0
#define SM_AHI   81920
#define SM_ALO   84480
#define SM_BLO   87040
#define SMEM_BYTES (92160 * 2)

// ---------------- device scratch (no allocation allowed) ----------------
__device__ __align__(16) __nv_bfloat16 g_Whi[(size_t)G4 * KTOT];
__device__ __align__(16) __nv_bfloat16 g_Wlo[(size_t)G4 * KTOT];
__device__ float g_bias[G4];
__device__ __align__(16) __nv_bfloat16 g_hHi[2][(size_t)Bb * Hh];
__device__ __align__(16) __nv_bfloat16 g_hLo[2][(size_t)Bb * Hh];
__device__ unsigned g_bar[8];
// Precomputed x @ W_ih^T + biases, layout [T][B][4H], fp32. 1 GiB static scratch.
__device__ float g_xw[(size_t)Tt * Bb * G4];

// ---------------- prep: bf16-split weights, fused bias, zero state ----------------
__global__ void prep_kernel(const float* __restrict__ Wih, const float* __restrict__ Whh,
                            const float* __restrict__ bih, const float* __restrict__ bhh)
{
    int idx = blockIdx.x * blockDim.x + threadIdx.x;
    int nthreads = gridDim.x * blockDim.x;
    const int total = G4 * KTOT;
    for (int i = idx; i < total; i += nthreads) {
        int j = i / KTOT;
        int k = i - j * KTOT;
        float v = (k < Ff) ? Wih[j * Ff + k] : Whh[j * Hh + (k - Ff)];
        __nv_bfloat16 hi = __float2bfloat16_rn(v);
        float lo = v - __bfloat162float(hi);
        g_Whi[i] = hi;
        g_Wlo[i] = __float2bfloat16_rn(lo);
    }
    if (idx < G4) g_bias[idx] = bih[idx] + bhh[idx];
    if (idx < 8) g_bar[idx] = 0u;
    __nv_bfloat16 z = __float2bfloat16_rn(0.f);
    for (int i = idx; i < Bb * Hh; i += nthreads) {
        g_hHi[0][i] = z;
        g_hLo[0][i] = z;
    }
}

// ---------------- bf16 mma helper ----------------
__device__ __forceinline__ void mma16816(float* d, const uint32_t* a, uint32_t b0, uint32_t b1)
{
    asm volatile(
        "mma.sync.aligned.m16n8k16.row.col.f32.bf16.bf16.f32 "
        "{%0,%1,%2,%3}, {%4,%5,%6,%7}, {%8,%9}, {%0,%1,%2,%3};\n"
        : "+f"(d[0]), "+f"(d[1]), "+f"(d[2]), "+f"(d[3])
        : "r"(a[0]), "r"(a[1]), "r"(a[2]), "r"(a[3]), "r"(b0), "r"(b1));
}

__device__ __forceinline__ void split_store(__nv_bfloat16* hi, __nv_bfloat16* lo, float4 v)
{
    __nv_bfloat16 hx = __float2bfloat16_rn(v.x);
    __nv_bfloat16 hy = __float2bfloat16_rn(v.y);
    __nv_bfloat16 hz = __float2bfloat16_rn(v.z);
    __nv_bfloat16 hw = __float2bfloat16_rn(v.w);
    *(__nv_bfloat162*)hi       = __halves2bfloat162(hx, hy);
    *(__nv_bfloat162*)(hi + 2) = __halves2bfloat162(hz, hw);
    *(__nv_bfloat162*)lo       = __halves2bfloat162(
        __float2bfloat16_rn(v.x - __bfloat162float(hx)),
        __float2bfloat16_rn(v.y - __bfloat162float(hy)));
    *(__nv_bfloat162*)(lo + 2) = __halves2bfloat162(
        __float2bfloat16_rn(v.z - __bfloat162float(hz)),
        __float2bfloat16_rn(v.w - __bfloat162float(hw)));
}

// Shared inner product: 3-term split mma over one KC=32 chunk resident in smem.
__device__ __forceinline__ void mma_chunk(const __nv_bfloat16* sAhi, const __nv_bfloat16* sAlo,
                                          const __nv_bfloat16* sBhi, const __nv_bfloat16* sBlo,
                                          int warp, int lane, float acc[16][4])
{
#pragma unroll
    for (int kk = 0; kk < KC; kk += 16) {
        const int arow = warp * 16 + (lane >> 2);
        const int acol = kk + ((lane & 3) << 1);
        uint32_t ahi[4], alo[4];
        ahi[0] = *(const uint32_t*)&sAhi[arow * KP + acol];
        ahi[1] = *(const uint32_t*)&sAhi[(arow + 8) * KP + acol];
        ahi[2] = *(const uint32_t*)&sAhi[arow * KP + acol + 8];
        ahi[3] = *(const uint32_t*)&sAhi[(arow + 8) * KP + acol + 8];
        alo[0] = *(const uint32_t*)&sAlo[arow * KP + acol];
        alo[1] = *(const uint32_t*)&sAlo[(arow + 8) * KP + acol];
        alo[2] = *(const uint32_t*)&sAlo[arow * KP + acol + 8];
        alo[3] = *(const uint32_t*)&sAlo[(arow + 8) * KP + acol + 8];
#pragma unroll
        for (int nf = 0; nf < 16; nf++) {
            int brow = nf * 8 + (lane >> 2);
            int bcol = kk + ((lane & 3) << 1);
            uint32_t bh0 = *(const uint32_t*)&sBhi[brow * KP + bcol];
            uint32_t bh1 = *(const uint32_t*)&sBhi[brow * KP + bcol + 8];
            uint32_t bl0 = *(const uint32_t*)&sBlo[brow * KP + bcol];
            uint32_t bl1 = *(const uint32_t*)&sBlo[brow * KP + bcol + 8];
            mma16816(acc[nf], ahi, bh0, bh1);
            mma16816(acc[nf], ahi, bl0, bl1);
            mma16816(acc[nf], alo, bh0, bh1);
        }
    }
}

// ---------------- precompute xw = x @ W_ih^T + (b_ih + b_hh) ----------------
// Fully parallel over (t, batch-block): grid.x = T * (B/BM) = 2048, grid.y = 16.
__global__ __launch_bounds__(128, 1)
void xw_kernel(const float* __restrict__ x)
{
    __shared__ __align__(16) __nv_bfloat16 sAhi[BM * KP];
    __shared__ __align__(16) __nv_bfloat16 sAlo[BM * KP];
    __shared__ __align__(16) __nv_bfloat16 sBhi[4 * BU * KP];
    __shared__ __align__(16) __nv_bfloat16 sBlo[4 * BU * KP];

    const int tid = threadIdx.x;
    const int warp = tid >> 5;
    const int lane = tid & 31;
    const int t  = blockIdx.x >> 3;
    const int m0 = (blockIdx.x & 7) * BM;
    const int u0 = blockIdx.y * BU;

    float acc[16][4];
#pragma unroll
    for (int i = 0; i < 16; i++)
#pragma unroll
        for (int j = 0; j < 4; j++) acc[i][j] = 0.f;

    for (int kc = 0; kc < Ff; kc += KC) {
#pragma unroll
        for (int i = 0; i < 4; i++) {
            int f4 = tid + i * 128;
            int row = f4 >> 3;
            int kq  = (f4 & 7) << 2;
            float4 v = *(const float4*)&x[((size_t)(m0 + row) * Tt + t) * Ff + kc + kq];
            split_store(&sAhi[row * KP + kq], &sAlo[row * KP + kq], v);
        }
        {
            int n = tid;
            int g = n >> 5, u = n & 31;
            size_t off = (size_t)(g * Hh + u0 + u) * KTOT + kc;   // x-part cols of fused W
            const uint4* wh = (const uint4*)&g_Whi[off];
            const uint4* wl = (const uint4*)&g_Wlo[off];
            uint4* dh = (uint4*)&sBhi[n * KP];
            uint4* dl = (uint4*)&sBlo[n * KP];
#pragma unroll
            for (int q = 0; q < 4; q++) { dh[q] = wh[q]; dl[q] = wl[q]; }
        }
        __syncthreads();
        mma_chunk(sAhi, sAlo, sBhi, sBlo, warp, lane, acc);
        __syncthreads();
    }

    // epilogue: xw[t][b][g*H + u] = acc + bias
    const int r = lane >> 2;
    const int cb = (lane & 3) << 1;
#pragma unroll
    for (int nf = 0; nf < 16; nf++) {
        int g = nf >> 2, q = nf & 3;
        int gidx = g * Hh + u0 + q * 8 + cb;
        float b0 = g_bias[gidx], b1 = g_bias[gidx + 1];
#pragma unroll
        for (int rr = 0; rr < 2; rr++) {
            int b = m0 + warp * 16 + r + rr * 8;
            float2 v = make_float2(acc[nf][rr * 2] + b0, acc[nf][rr * 2 + 1] + b1);
            *(float2*)&g_xw[((size_t)t * Bb + b) * G4 + gidx] = v;
        }
    }
}

// ---------------- persistent LSTM chain: all 256 steps in one launch ----------------
// 128 CTAs (1/SM, all co-resident). Dependency is confined to a batch-group:
// the 16 CTAs sharing m_blk exchange h through L2 with a per-group software barrier.
// c lives in registers for the whole chain; B-hi weights live in smem for the whole chain.
__global__ __launch_bounds__(128, 1)
void lstm_persist_kernel()
{
    extern __shared__ __align__(16) __nv_bfloat16 smp[];
    __nv_bfloat16* sBHi = smp + SM_BHI;
    __nv_bfloat16* sAhi = smp + SM_AHI;
    __nv_bfloat16* sAlo = smp + SM_ALO;
    __nv_bfloat16* sBlo = smp + SM_BLO;

    const int tid = threadIdx.x;
    const int warp = tid >> 5;
    const int lane = tid & 31;
    const int m_blk = blockIdx.x & 7;
    const int u_blk = blockIdx.x >> 3;
    const int m0 = m_blk * BM;
    const int u0 = u_blk * BU;
    const int r = lane >> 2;
    const int cb = (lane & 3) << 1;

    // ---- load persistent B-hi (h-part weights for this CTA's 128 gate rows) ----
    {
        int n = tid;
        int g = n >> 5, u = n & 31;
#pragma unroll
        for (int kcIdx = 0; kcIdx < NCHUNK; kcIdx++) {
            size_t off = (size_t)(g * Hh + u0 + u) * KTOT + Ff + kcIdx * KC;
            const uint4* wh = (const uint4*)&g_Whi[off];
            uint4* dh = (uint4*)&sBHi[kcIdx * CHUNK_ELEMS + n * KP];
#pragma unroll
            for (int q = 0; q < 4; q++) dh[q] = wh[q];
        }
    }

    float creg[16];
#pragma unroll
    for (int i = 0; i < 16; i++) creg[i] = 0.f;

    __syncthreads();

    for (int t = 0; t < Tt; t++) {
        const int src = t & 1;
        const int dst = src ^ 1;

        // accumulator init = precomputed x-part (+ biases, already folded)
        float acc[16][4];
#pragma unroll
        for (int nf = 0; nf < 16; nf++) {
            int g = nf >> 2, q = nf & 3;
            int gidx = g * Hh + u0 + q * 8 + cb;
#pragma unroll
            for (int rr = 0; rr < 2; rr++) {
                int b = m0 + warp * 16 + r + rr * 8;
                float2 v = *(const float2*)&g_xw[((size_t)t * Bb + b) * G4 + gidx];
                acc[nf][rr * 2] = v.x;
                acc[nf][rr * 2 + 1] = v.y;
            }
        }

        const __nv_bfloat16* hHi = g_hHi[src];
        const __nv_bfloat16* hLo = g_hLo[src];

        for (int kcIdx = 0; kcIdx < NCHUNK; kcIdx++) {
            const int kc = kcIdx * KC;
            // A tile: pre-split h, __ldcg (L2 is the cross-CTA coherence point)
#pragma unroll
            for (int i = 0; i < 2; i++) {
                int f4 = tid + i * 128;            // 0..255 (64 rows x 4 uint4)
                int row = f4 >> 2;
                int kq  = (f4 & 3) << 3;
                size_t gi = (size_t)(m0 + row) * Hh + kc + kq;
                uint4 vh = __ldcg((const uint4*)&hHi[gi]);
                uint4 vl = __ldcg((const uint4*)&hLo[gi]);
                *(uint4*)&sAhi[row * KP + kq] = vh;
                *(uint4*)&sAlo[row * KP + kq] = vl;
            }
            // B-lo streamed chunk (L2-resident, 2 MB total)
            {
                int n = tid;
                int g = n >> 5, u = n & 31;
                size_t off = (size_t)(g * Hh + u0 + u) * KTOT + Ff + kc;
                const uint4* wl = (const uint4*)&g_Wlo[off];
                uint4* dl = (uint4*)&sBlo[n * KP];
#pragma unroll
                for (int q = 0; q < 4; q++) dl[q] = wl[q];
            }
            __syncthreads();
            mma_chunk(sAhi, sAlo, &sBHi[kcIdx * CHUNK_ELEMS], sBlo, warp, lane, acc);
            __syncthreads();
        }

        // pointwise LSTM update; c in registers; h written pre-split bf16 hi/lo
        __nv_bfloat16* oHi = g_hHi[dst];
        __nv_bfloat16* oLo = g_hLo[dst];
#pragma unroll
        for (int q = 0; q < 4; q++) {
#pragma unroll
            for (int rr = 0; rr < 2; rr++) {
                int b = m0 + warp * 16 + r + rr * 8;
                float hv[2];
#pragma unroll
                for (int p = 0; p < 2; p++) {
                    int di = rr * 2 + p;
                    int ci = q * 4 + rr * 2 + p;
                    float pi = acc[q][di];
                    float pf = acc[4 + q][di];
                    float pg = acc[8 + q][di];
                    float po = acc[12 + q][di];
                    float ig = 1.f / (1.f + expf(-pi));
                    float fg = 1.f / (1.f + expf(-pf));
                    float gv = tanhf(pg);
                    float og = 1.f / (1.f + expf(-po));
                    float cv = fg * creg[ci] + ig * gv;
                    creg[ci] = cv;
                    hv[p] = og * tanhf(cv);
                }
                int u = u0 + q * 8 + cb;
                __nv_bfloat16 h0 = __float2bfloat16_rn(hv[0]);
                __nv_bfloat16 h1 = __float2bfloat16_rn(hv[1]);
                size_t oi = (size_t)b * Hh + u;
                *(__nv_bfloat162*)&oHi[oi] = __halves2bfloat162(h0, h1);
                *(__nv_bfloat162*)&oLo[oi] = __halves2bfloat162(
                    __float2bfloat16_rn(hv[0] - __bfloat162float(h0)),
                    __float2bfloat16_rn(hv[1] - __bfloat162float(h1)));
            }
        }

        // per-group software barrier (16 CTAs sharing m_blk)
        __syncthreads();                    // all CTA threads done writing h
        if (tid == 0) {
            __threadfence();                // make h visible gpu-wide (cumulative)
            atomicAdd(&g_bar[m_blk], 1u);
            unsigned target = 16u * (unsigned)(t + 1);
            while (atomicAdd(&g_bar[m_blk], 0u) < target) { }
        }
        __syncthreads();
    }
}

// ---------------- output head: out[b] = h_T[b] . W_out + b_out ----------------
__global__ void head_kernel(const float* __restrict__ Wout, const float* __restrict__ bout,
                            float* __restrict__ out)
{
    int b = blockIdx.x * 4 + (threadIdx.x >> 5);
    int lane = threadIdx.x & 31;
    const __nv_bfloat16* hi = &g_hHi[0][(size_t)b * Hh];
    const __nv_bfloat16* lo = &g_hLo[0][(size_t)b * Hh];
    float s = 0.f;
#pragma unroll
    for (int u = lane; u < Hh; u += 32) {
        float h = __bfloat162float(hi[u]) + __bfloat162float(lo[u]);
        s += h * Wout[u];
    }
#pragma unroll
    for (int o = 16; o; o >>= 1) s += __shfl_xor_sync(0xffffffffu, s, o);
    if (lane == 0) out[b] = s + bout[0];
}

extern "C" void kernel_launch(void* const* d_in, const int* in_sizes, int n_in,
                              void* d_out, int out_size)
{
    const float* x    = (const float*)d_in[0];
    const float* Wih  = (const float*)d_in[1];
    const float* Whh  = (const float*)d_in[2];
    const float* bih  = (const float*)d_in[3];
    const float* bhh  = (const float*)d_in[4];
    const float* Wout = (const float*)d_in[5];
    const float* bout = (const float*)d_in[6];
    float* out = (float*)d_out;

    static bool attr_set = false;
    if (!attr_set) {
        cudaFuncSetAttribute(lstm_persist_kernel,
                             cudaFuncAttributeMaxDynamicSharedMemorySize, SMEM_BYTES);
        attr_set = true;
    }

    prep_kernel<<<512, 256>>>(Wih, Whh, bih, bhh);

    dim3 xgrid(Tt * (Bb / BM), Hh / BU);       // (2048, 16)
    xw_kernel<<<xgrid, 128>>>(x);

    lstm_persist_kernel<<<128, 128, SMEM_BYTES>>>();

    head_kernel<<<Bb / 4, 128>>>(Wout, bout, out);
}

// round 4
// speedup vs baseline: 1.3743x; 1.3743x over previous
#include <cuda_runtime.h>
#include <cuda_bf16.h>
#include <cstdint>

#define Bb 512
#define Tt 256
#define Ff 256
#define Hh 512
#define KTOT (Ff + Hh)          /* 768 */
#define G4 (4 * Hh)             /* 2048 */

#define BM 64
#define BU 32
#define KC 32
#define KP 40                   /* padded K stride in bf16 elems -> conflict-free LDS */
#define NCHUNK (Hh / KC)        /* 16 h-part K chunks */
#define CHUNK_ELEMS (4 * BU * KP)   /* 5120 bf16 per B chunk */

// ---- persist dynamic smem layout (bf16 elems) ----
//   [0, 81920)              persistent B-hi (16 chunks x 5120)
//   stage s (s=0,1) at 81920 + s*10240:
//     +0     sAhi (64 x 40 = 2560)
//     +2560  sAlo (2560)
//     +5120  sBlo (5120)
#define P_SM_BHI     0
#define P_STAGE_BASE 81920
#define P_STAGE_ELEMS 10240
#define P_OFF_AHI 0
#define P_OFF_ALO 2560
#define P_OFF_BLO 5120
#define SMEM_P_BYTES ((P_STAGE_BASE + 2 * P_STAGE_ELEMS) * 2)   /* 204800 */

// ---- xw dynamic smem layout (bf16 elems) ----
// stage s at s*15360: sAhi 2560 | sAlo 2560 | sBhi 5120 | sBlo 5120
#define X_STAGE_ELEMS 15360
#define X_OFF_AHI 0
#define X_OFF_ALO 2560
#define X_OFF_BHI 5120
#define X_OFF_BLO 10240
#define SMEM_X_BYTES (2 * X_STAGE_ELEMS * 2)                    /* 61440 */

// ---------------- device scratch (no allocation allowed) ----------------
__device__ __align__(16) __nv_bfloat16 g_Whi[(size_t)G4 * KTOT];
__device__ __align__(16) __nv_bfloat16 g_Wlo[(size_t)G4 * KTOT];
__device__ float g_bias[G4];
__device__ __align__(16) __nv_bfloat16 g_hHi[2][(size_t)Bb * Hh];
__device__ __align__(16) __nv_bfloat16 g_hLo[2][(size_t)Bb * Hh];
__device__ __align__(16) __nv_bfloat16 g_xHi[(size_t)Bb * Tt * Ff];
__device__ __align__(16) __nv_bfloat16 g_xLo[(size_t)Bb * Tt * Ff];
__device__ unsigned g_bar[8];
// Precomputed x @ W_ih^T + biases, layout [T][B][4H], fp32. 1 GiB static scratch.
__device__ float g_xw[(size_t)Tt * Bb * G4];

// ---------------- cp.async helpers ----------------
__device__ __forceinline__ void cp_async16(void* smem_ptr, const void* gmem_ptr)
{
    uint32_t s = (uint32_t)__cvta_generic_to_shared(smem_ptr);
    asm volatile("cp.async.cg.shared.global [%0], [%1], 16;\n" :: "r"(s), "l"(gmem_ptr));
}
__device__ __forceinline__ void cp_commit() { asm volatile("cp.async.commit_group;\n" ::); }
__device__ __forceinline__ void cp_wait0()  { asm volatile("cp.async.wait_group 0;\n" ::); }
__device__ __forceinline__ void cp_wait1()  { asm volatile("cp.async.wait_group 1;\n" ::); }

// ---------------- prep: bf16-split weights AND x, fused bias, zero state ----------------
__global__ void prep_kernel(const float* __restrict__ x,
                            const float* __restrict__ Wih, const float* __restrict__ Whh,
                            const float* __restrict__ bih, const float* __restrict__ bhh)
{
    int idx = blockIdx.x * blockDim.x + threadIdx.x;
    int nthreads = gridDim.x * blockDim.x;
    const int total = G4 * KTOT;
    for (int i = idx; i < total; i += nthreads) {
        int j = i / KTOT;
        int k = i - j * KTOT;
        float v = (k < Ff) ? Wih[j * Ff + k] : Whh[j * Hh + (k - Ff)];
        __nv_bfloat16 hi = __float2bfloat16_rn(v);
        g_Whi[i] = hi;
        g_Wlo[i] = __float2bfloat16_rn(v - __bfloat162float(hi));
    }
    const int xtotal = Bb * Tt * Ff;
    for (int i = idx; i < xtotal; i += nthreads) {
        float v = x[i];
        __nv_bfloat16 hi = __float2bfloat16_rn(v);
        g_xHi[i] = hi;
        g_xLo[i] = __float2bfloat16_rn(v - __bfloat162float(hi));
    }
    if (idx < G4) g_bias[idx] = bih[idx] + bhh[idx];
    if (idx < 8) g_bar[idx] = 0u;
    __nv_bfloat16 z = __float2bfloat16_rn(0.f);
    for (int i = idx; i < Bb * Hh; i += nthreads) {
        g_hHi[0][i] = z;
        g_hLo[0][i] = z;
    }
}

// ---------------- bf16 mma helper ----------------
__device__ __forceinline__ void mma16816(float* d, const uint32_t* a, uint32_t b0, uint32_t b1)
{
    asm volatile(
        "mma.sync.aligned.m16n8k16.row.col.f32.bf16.bf16.f32 "
        "{%0,%1,%2,%3}, {%4,%5,%6,%7}, {%8,%9}, {%0,%1,%2,%3};\n"
        : "+f"(d[0]), "+f"(d[1]), "+f"(d[2]), "+f"(d[3])
        : "r"(a[0]), "r"(a[1]), "r"(a[2]), "r"(a[3]), "r"(b0), "r"(b1));
}

// Shared inner product: 3-term split mma over one KC=32 chunk resident in smem.
__device__ __forceinline__ void mma_chunk(const __nv_bfloat16* sAhi, const __nv_bfloat16* sAlo,
                                          const __nv_bfloat16* sBhi, const __nv_bfloat16* sBlo,
                                          int warp, int lane, float acc[16][4])
{
#pragma unroll
    for (int kk = 0; kk < KC; kk += 16) {
        const int arow = warp * 16 + (lane >> 2);
        const int acol = kk + ((lane & 3) << 1);
        uint32_t ahi[4], alo[4];
        ahi[0] = *(const uint32_t*)&sAhi[arow * KP + acol];
        ahi[1] = *(const uint32_t*)&sAhi[(arow + 8) * KP + acol];
        ahi[2] = *(const uint32_t*)&sAhi[arow * KP + acol + 8];
        ahi[3] = *(const uint32_t*)&sAhi[(arow + 8) * KP + acol + 8];
        alo[0] = *(const uint32_t*)&sAlo[arow * KP + acol];
        alo[1] = *(const uint32_t*)&sAlo[(arow + 8) * KP + acol];
        alo[2] = *(const uint32_t*)&sAlo[arow * KP + acol + 8];
        alo[3] = *(const uint32_t*)&sAlo[(arow + 8) * KP + acol + 8];
#pragma unroll
        for (int nf = 0; nf < 16; nf++) {
            int brow = nf * 8 + (lane >> 2);
            int bcol = kk + ((lane & 3) << 1);
            uint32_t bh0 = *(const uint32_t*)&sBhi[brow * KP + bcol];
            uint32_t bh1 = *(const uint32_t*)&sBhi[brow * KP + bcol + 8];
            uint32_t bl0 = *(const uint32_t*)&sBlo[brow * KP + bcol];
            uint32_t bl1 = *(const uint32_t*)&sBlo[brow * KP + bcol + 8];
            mma16816(acc[nf], ahi, bh0, bh1);
            mma16816(acc[nf], ahi, bl0, bl1);
            mma16816(acc[nf], alo, bh0, bh1);
        }
    }
}

// ---------------- precompute xw = x @ W_ih^T + (b_ih + b_hh) ----------------
// Fully parallel over (t, batch-block). Double-buffered cp.async pipeline.
__global__ __launch_bounds__(128, 1)
void xw_kernel()
{
    extern __shared__ __align__(16) __nv_bfloat16 smx[];

    const int tid = threadIdx.x;
    const int warp = tid >> 5;
    const int lane = tid & 31;
    const int t  = blockIdx.x >> 3;
    const int m0 = (blockIdx.x & 7) * BM;
    const int u0 = blockIdx.y * BU;

    auto issue = [&](int stage, int kc) {
        __nv_bfloat16* st = smx + stage * X_STAGE_ELEMS;
#pragma unroll
        for (int i = 0; i < 2; i++) {                 // A hi/lo: 64 rows x 32
            int c = tid + i * 128;
            int row = c >> 2, kq = (c & 3) << 3;
            size_t gi = ((size_t)(m0 + row) * Tt + t) * Ff + kc + kq;
            cp_async16(&st[X_OFF_AHI + row * KP + kq], &g_xHi[gi]);
            cp_async16(&st[X_OFF_ALO + row * KP + kq], &g_xLo[gi]);
        }
#pragma unroll
        for (int i = 0; i < 4; i++) {                 // B hi/lo: 128 rows x 32
            int c = tid + i * 128;
            int n = c >> 2, kq = (c & 3) << 3;
            int g = n >> 5, u = n & 31;
            size_t off = (size_t)(g * Hh + u0 + u) * KTOT + kc + kq;
            cp_async16(&st[X_OFF_BHI + n * KP + kq], &g_Whi[off]);
            cp_async16(&st[X_OFF_BLO + n * KP + kq], &g_Wlo[off]);
        }
        cp_commit();
    };

    float acc[16][4];
#pragma unroll
    for (int i = 0; i < 16; i++)
#pragma unroll
        for (int j = 0; j < 4; j++) acc[i][j] = 0.f;

    const int NX = Ff / KC;   // 8
    issue(0, 0);
    for (int kcIdx = 0; kcIdx < NX; kcIdx++) {
        int stage = kcIdx & 1;
        if (kcIdx + 1 < NX) { issue(stage ^ 1, (kcIdx + 1) * KC); cp_wait1(); }
        else cp_wait0();
        __syncthreads();
        __nv_bfloat16* st = smx + stage * X_STAGE_ELEMS;
        mma_chunk(st + X_OFF_AHI, st + X_OFF_ALO, st + X_OFF_BHI, st + X_OFF_BLO,
                  warp, lane, acc);
        __syncthreads();
    }

    // epilogue: xw[t][b][g*H + u] = acc + bias
    const int r = lane >> 2;
    const int cb = (lane & 3) << 1;
#pragma unroll
    for (int nf = 0; nf < 16; nf++) {
        int g = nf >> 2, q = nf & 3;
        int gidx = g * Hh + u0 + q * 8 + cb;
        float b0 = g_bias[gidx], b1 = g_bias[gidx + 1];
#pragma unroll
        for (int rr = 0; rr < 2; rr++) {
            int b = m0 + warp * 16 + r + rr * 8;
            float2 v = make_float2(acc[nf][rr * 2] + b0, acc[nf][rr * 2 + 1] + b1);
            *(float2*)&g_xw[((size_t)t * Bb + b) * G4 + gidx] = v;
        }
    }
}

// ---------------- persistent LSTM chain: all 256 steps in one launch ----------------
// 128 CTAs (1/SM, all co-resident). 16-CTA batch-groups exchange h through L2 with a
// per-group software barrier. c in registers; B-hi in smem for the whole chain.
// Streamed tiles (h hi/lo, B-lo) are double-buffered via cp.async.cg (L1-bypass ->
// reads land in L2, the coherence point for the peer-written h).
__global__ __launch_bounds__(128, 1)
void lstm_persist_kernel()
{
    extern __shared__ __align__(16) __nv_bfloat16 smp[];
    __nv_bfloat16* sBHi = smp + P_SM_BHI;

    const int tid = threadIdx.x;
    const int warp = tid >> 5;
    const int lane = tid & 31;
    const int m_blk = blockIdx.x & 7;
    const int u_blk = blockIdx.x >> 3;
    const int m0 = m_blk * BM;
    const int u0 = u_blk * BU;
    const int r = lane >> 2;
    const int cb = (lane & 3) << 1;

    // ---- load persistent B-hi (h-part weights for this CTA's 128 gate rows) ----
    {
        int n = tid;
        int g = n >> 5, u = n & 31;
#pragma unroll
        for (int kcIdx = 0; kcIdx < NCHUNK; kcIdx++) {
            size_t off = (size_t)(g * Hh + u0 + u) * KTOT + Ff + kcIdx * KC;
            const uint4* wh = (const uint4*)&g_Whi[off];
            uint4* dh = (uint4*)&sBHi[kcIdx * CHUNK_ELEMS + n * KP];
#pragma unroll
            for (int q = 0; q < 4; q++) dh[q] = wh[q];
        }
    }

    float creg[16];
#pragma unroll
    for (int i = 0; i < 16; i++) creg[i] = 0.f;

    __syncthreads();

    for (int t = 0; t < Tt; t++) {
        const int src = t & 1;
        const int dst = src ^ 1;
        const __nv_bfloat16* hHi = g_hHi[src];
        const __nv_bfloat16* hLo = g_hLo[src];

        auto issue = [&](int stage, int kc) {
            __nv_bfloat16* st = smp + P_STAGE_BASE + stage * P_STAGE_ELEMS;
#pragma unroll
            for (int i = 0; i < 2; i++) {             // A hi/lo: 64 rows x 32
                int c = tid + i * 128;
                int row = c >> 2, kq = (c & 3) << 3;
                size_t gi = (size_t)(m0 + row) * Hh + kc + kq;
                cp_async16(&st[P_OFF_AHI + row * KP + kq], &hHi[gi]);
                cp_async16(&st[P_OFF_ALO + row * KP + kq], &hLo[gi]);
            }
#pragma unroll
            for (int i = 0; i < 4; i++) {             // B-lo: 128 rows x 32
                int c = tid + i * 128;
                int n = c >> 2, kq = (c & 3) << 3;
                int g = n >> 5, u = n & 31;
                size_t off = (size_t)(g * Hh + u0 + u) * KTOT + Ff + kc + kq;
                cp_async16(&st[P_OFF_BLO + n * KP + kq], &g_Wlo[off]);
            }
            cp_commit();
        };

        // accumulator init = precomputed x-part (+ biases, already folded)
        float acc[16][4];
#pragma unroll
        for (int nf = 0; nf < 16; nf++) {
            int g = nf >> 2, q = nf & 3;
            int gidx = g * Hh + u0 + q * 8 + cb;
#pragma unroll
            for (int rr = 0; rr < 2; rr++) {
                int b = m0 + warp * 16 + r + rr * 8;
                float2 v = *(const float2*)&g_xw[((size_t)t * Bb + b) * G4 + gidx];
                acc[nf][rr * 2] = v.x;
                acc[nf][rr * 2 + 1] = v.y;
            }
        }

        issue(0, 0);
        for (int kcIdx = 0; kcIdx < NCHUNK; kcIdx++) {
            int stage = kcIdx & 1;
            if (kcIdx + 1 < NCHUNK) { issue(stage ^ 1, (kcIdx + 1) * KC); cp_wait1(); }
            else cp_wait0();
            __syncthreads();
            __nv_bfloat16* st = smp + P_STAGE_BASE + stage * P_STAGE_ELEMS;
            mma_chunk(st + P_OFF_AHI, st + P_OFF_ALO,
                      &sBHi[kcIdx * CHUNK_ELEMS], st + P_OFF_BLO, warp, lane, acc);
            __syncthreads();
        }

        // pointwise LSTM update; c in registers; h written pre-split bf16 hi/lo
        __nv_bfloat16* oHi = g_hHi[dst];
        __nv_bfloat16* oLo = g_hLo[dst];
#pragma unroll
        for (int q = 0; q < 4; q++) {
#pragma unroll
            for (int rr = 0; rr < 2; rr++) {
                int b = m0 + warp * 16 + r + rr * 8;
                float hv[2];
#pragma unroll
                for (int p = 0; p < 2; p++) {
                    int di = rr * 2 + p;
                    int ci = q * 4 + rr * 2 + p;
                    float pi = acc[q][di];
                    float pf = acc[4 + q][di];
                    float pg = acc[8 + q][di];
                    float po = acc[12 + q][di];
                    float ig = 1.f / (1.f + expf(-pi));
                    float fg = 1.f / (1.f + expf(-pf));
                    float gv = tanhf(pg);
                    float og = 1.f / (1.f + expf(-po));
                    float cv = fg * creg[ci] + ig * gv;
                    creg[ci] = cv;
                    hv[p] = og * tanhf(cv);
                }
                int u = u0 + q * 8 + cb;
                __nv_bfloat16 h0 = __float2bfloat16_rn(hv[0]);
                __nv_bfloat16 h1 = __float2bfloat16_rn(hv[1]);
                size_t oi = (size_t)b * Hh + u;
                *(__nv_bfloat162*)&oHi[oi] = __halves2bfloat162(h0, h1);
                *(__nv_bfloat162*)&oLo[oi] = __halves2bfloat162(
                    __float2bfloat16_rn(hv[0] - __bfloat162float(h0)),
                    __float2bfloat16_rn(hv[1] - __bfloat162float(h1)));
            }
        }

        // per-group software barrier (16 CTAs sharing m_blk)
        __syncthreads();                    // all CTA threads done writing h
        if (tid == 0) {
            __threadfence();                // make h visible gpu-wide (cumulative)
            atomicAdd(&g_bar[m_blk], 1u);
            unsigned target = 16u * (unsigned)(t + 1);
            while (atomicAdd(&g_bar[m_blk], 0u) < target) { }
        }
        __syncthreads();
    }
}

// ---------------- output head: out[b] = h_T[b] . W_out + b_out ----------------
__global__ void head_kernel(const float* __restrict__ Wout, const float* __restrict__ bout,
                            float* __restrict__ out)
{
    int b = blockIdx.x * 4 + (threadIdx.x >> 5);
    int lane = threadIdx.x & 31;
    const __nv_bfloat16* hi = &g_hHi[0][(size_t)b * Hh];
    const __nv_bfloat16* lo = &g_hLo[0][(size_t)b * Hh];
    float s = 0.f;
#pragma unroll
    for (int u = lane; u < Hh; u += 32) {
        float h = __bfloat162float(hi[u]) + __bfloat162float(lo[u]);
        s += h * Wout[u];
    }
#pragma unroll
    for (int o = 16; o; o >>= 1) s += __shfl_xor_sync(0xffffffffu, s, o);
    if (lane == 0) out[b] = s + bout[0];
}

extern "C" void kernel_launch(void* const* d_in, const int* in_sizes, int n_in,
                              void* d_out, int out_size)
{
    const float* x    = (const float*)d_in[0];
    const float* Wih  = (const float*)d_in[1];
    const float* Whh  = (const float*)d_in[2];
    const float* bih  = (const float*)d_in[3];
    const float* bhh  = (const float*)d_in[4];
    const float* Wout = (const float*)d_in[5];
    const float* bout = (const float*)d_in[6];
    float* out = (float*)d_out;

    static bool attr_set = false;
    if (!attr_set) {
        cudaFuncSetAttribute(lstm_persist_kernel,
                             cudaFuncAttributeMaxDynamicSharedMemorySize, SMEM_P_BYTES);
        cudaFuncSetAttribute(xw_kernel,
                             cudaFuncAttributeMaxDynamicSharedMemorySize, SMEM_X_BYTES);
        attr_set = true;
    }

    prep_kernel<<<512, 256>>>(x, Wih, Whh, bih, bhh);

    dim3 xgrid(Tt * (Bb / BM), Hh / BU);       // (2048, 16)
    xw_kernel<<<xgrid, 128, SMEM_X_BYTES>>>();

    lstm_persist_kernel<<<128, 128, SMEM_P_BYTES>>>();

    head_kernel<<<Bb / 4, 128>>>(Wout, bout, out);
}

// round 14
// speedup vs baseline: 1.7239x; 1.2543x over previous
#include <cuda_runtime.h>
#include <cuda_fp16.h>
#include <cstdint>

#define Bb 512
#define Tt 256
#define Ff 256
#define Hh 512
#define KTOT (Ff + Hh)          /* 768 */
#define G4 (4 * Hh)             /* 2048 */

#define BM 64
#define BU 32
#define KC 32
#define KP 40                   /* padded K stride in fp16 elems -> conflict-free LDS */
#define NCHUNK (Hh / KC)        /* 16 h-part K chunks */
#define CHUNK_ELEMS (4 * BU * KP)   /* 5120 fp16 per B chunk */

// ---- persist dynamic smem layout (fp16 elems) ----
//   [0, 81920)  persistent B-hi (16 chunks x 5120)
//   stage s (s=0,1) at 81920 + s*7680:  +0 sA (2560) | +2560 sBlo (5120)
#define P_SM_BHI      0
#define P_STAGE_BASE  81920
#define P_STAGE_ELEMS 7680
#define P_OFF_A   0
#define P_OFF_BLO 2560
#define SMEM_P_BYTES ((P_STAGE_BASE + 2 * P_STAGE_ELEMS) * 2)   /* 194560 */

// ---- xw dynamic smem layout (fp16 elems) ----
// stage s at s*12800: sA 2560 | sBhi 5120 | sBlo 5120
#define X_STAGE_ELEMS 12800
#define X_OFF_A   0
#define X_OFF_BHI 2560
#define X_OFF_BLO 7680
#define SMEM_X_BYTES (2 * X_STAGE_ELEMS * 2)                    /* 51200 */

// ---------------- device scratch (no allocation allowed) ----------------
__device__ __align__(16) __half g_Whi[(size_t)G4 * KTOT];
__device__ __align__(16) __half g_Wlo[(size_t)G4 * KTOT];
__device__ float g_bias[G4];
__device__ __align__(16) __half g_h[2][(size_t)Bb * Hh];
__device__ __align__(16) __half g_xh[(size_t)Bb * Tt * Ff];
__device__ unsigned g_bar[8];
// Precomputed x @ W_ih^T + biases, layout [T][B][4H], fp32. 1 GiB static scratch.
__device__ float g_xw[(size_t)Tt * Bb * G4];

// ---------------- cp.async helpers ----------------
__device__ __forceinline__ void cp_async16(void* smem_ptr, const void* gmem_ptr)
{
    uint32_t s = (uint32_t)__cvta_generic_to_shared(smem_ptr);
    asm volatile("cp.async.cg.shared.global [%0], [%1], 16;\n" :: "r"(s), "l"(gmem_ptr));
}
__device__ __forceinline__ void cp_commit() { asm volatile("cp.async.commit_group;\n" ::); }
__device__ __forceinline__ void cp_wait0()  { asm volatile("cp.async.wait_group 0;\n" ::); }
__device__ __forceinline__ void cp_wait1()  { asm volatile("cp.async.wait_group 1;\n" ::); }

// ---------------- prep: fp16-split weights, fp16 x, fused bias, zero state ----------------
__global__ void prep_kernel(const float* __restrict__ x,
                            const float* __restrict__ Wih, const float* __restrict__ Whh,
                            const float* __restrict__ bih, const float* __restrict__ bhh)
{
    int idx = blockIdx.x * blockDim.x + threadIdx.x;
    int nthreads = gridDim.x * blockDim.x;
    const int total = G4 * KTOT;
    for (int i = idx; i < total; i += nthreads) {
        int j = i / KTOT;
        int k = i - j * KTOT;
        float v = (k < Ff) ? Wih[j * Ff + k] : Whh[j * Hh + (k - Ff)];
        __half hi = __float2half_rn(v);
        g_Whi[i] = hi;
        g_Wlo[i] = __float2half_rn(v - __half2float(hi));
    }
    const int xtotal = Bb * Tt * Ff;
    for (int i = idx; i < xtotal; i += nthreads)
        g_xh[i] = __float2half_rn(x[i]);
    if (idx < G4) g_bias[idx] = bih[idx] + bhh[idx];
    if (idx < 8) g_bar[idx] = 0u;
    __half z = __float2half_rn(0.f);
    for (int i = idx; i < Bb * Hh; i += nthreads)
        g_h[0][i] = z;
}

// ---------------- fp16 mma helper ----------------
__device__ __forceinline__ void mma16816(float* d, const uint32_t* a, uint32_t b0, uint32_t b1)
{
    asm volatile(
        "mma.sync.aligned.m16n8k16.row.col.f32.f16.f16.f32 "
        "{%0,%1,%2,%3}, {%4,%5,%6,%7}, {%8,%9}, {%0,%1,%2,%3};\n"
        : "+f"(d[0]), "+f"(d[1]), "+f"(d[2]), "+f"(d[3])
        : "r"(a[0]), "r"(a[1]), "r"(a[2]), "r"(a[3]), "r"(b0), "r"(b1));
}

// 2-term split mma over one KC=32 chunk: D += A*(Bhi) + A*(Blo)
__device__ __forceinline__ void mma_chunk(const __half* sA,
                                          const __half* sBhi, const __half* sBlo,
                                          int warp, int lane, float acc[16][4])
{
#pragma unroll
    for (int kk = 0; kk < KC; kk += 16) {
        const int arow = warp * 16 + (lane >> 2);
        const int acol = kk + ((lane & 3) << 1);
        uint32_t a[4];
        a[0] = *(const uint32_t*)&sA[arow * KP + acol];
        a[1] = *(const uint32_t*)&sA[(arow + 8) * KP + acol];
        a[2] = *(const uint32_t*)&sA[arow * KP + acol + 8];
        a[3] = *(const uint32_t*)&sA[(arow + 8) * KP + acol + 8];
#pragma unroll
        for (int nf = 0; nf < 16; nf++) {
            int brow = nf * 8 + (lane >> 2);
            int bcol = kk + ((lane & 3) << 1);
            uint32_t bh0 = *(const uint32_t*)&sBhi[brow * KP + bcol];
            uint32_t bh1 = *(const uint32_t*)&sBhi[brow * KP + bcol + 8];
            uint32_t bl0 = *(const uint32_t*)&sBlo[brow * KP + bcol];
            uint32_t bl1 = *(const uint32_t*)&sBlo[brow * KP + bcol + 8];
            mma16816(acc[nf], a, bh0, bh1);
            mma16816(acc[nf], a, bl0, bl1);
        }
    }
}

// ---------------- precompute xw = x @ W_ih^T + (b_ih + b_hh) ----------------
// Fully parallel over (t, batch-block). Double-buffered cp.async pipeline.
__global__ __launch_bounds__(128, 1)
void xw_kernel()
{
    extern __shared__ __align__(16) __half smx[];

    const int tid = threadIdx.x;
    const int warp = tid >> 5;
    const int lane = tid & 31;
    const int t  = blockIdx.x >> 3;
    const int m0 = (blockIdx.x & 7) * BM;
    const int u0 = blockIdx.y * BU;

    auto issue = [&](int stage, int kc) {
        __half* st = smx + stage * X_STAGE_ELEMS;
#pragma unroll
        for (int i = 0; i < 2; i++) {                 // A: 64 rows x 32
            int c = tid + i * 128;
            int row = c >> 2, kq = (c & 3) << 3;
            size_t gi = ((size_t)(m0 + row) * Tt + t) * Ff + kc + kq;
            cp_async16(&st[X_OFF_A + row * KP + kq], &g_xh[gi]);
        }
#pragma unroll
        for (int i = 0; i < 4; i++) {                 // B hi/lo: 128 rows x 32
            int c = tid + i * 128;
            int n = c >> 2, kq = (c & 3) << 3;
            int g = n >> 5, u = n & 31;
            size_t off = (size_t)(g * Hh + u0 + u) * KTOT + kc + kq;
            cp_async16(&st[X_OFF_BHI + n * KP + kq], &g_Whi[off]);
            cp_async16(&st[X_OFF_BLO + n * KP + kq], &g_Wlo[off]);
        }
        cp_commit();
    };

    float acc[16][4];
#pragma unroll
    for (int i = 0; i < 16; i++)
#pragma unroll
        for (int j = 0; j < 4; j++) acc[i][j] = 0.f;

    const int NX = Ff / KC;   // 8
    issue(0, 0);
    for (int kcIdx = 0; kcIdx < NX; kcIdx++) {
        int stage = kcIdx & 1;
        if (kcIdx + 1 < NX) { issue(stage ^ 1, (kcIdx + 1) * KC); cp_wait1(); }
        else cp_wait0();
        __syncthreads();
        __half* st = smx + stage * X_STAGE_ELEMS;
        mma_chunk(st + X_OFF_A, st + X_OFF_BHI, st + X_OFF_BLO, warp, lane, acc);
        __syncthreads();
    }

    // epilogue: xw[t][b][g*H + u] = acc + bias
    const int r = lane >> 2;
    const int cb = (lane & 3) << 1;
#pragma unroll
    for (int nf = 0; nf < 16; nf++) {
        int g = nf >> 2, q = nf & 3;
        int gidx = g * Hh + u0 + q * 8 + cb;
        float b0 = g_bias[gidx], b1 = g_bias[gidx + 1];
#pragma unroll
        for (int rr = 0; rr < 2; rr++) {
            int b = m0 + warp * 16 + r + rr * 8;
            float2 v = make_float2(acc[nf][rr * 2] + b0, acc[nf][rr * 2 + 1] + b1);
            *(float2*)&g_xw[((size_t)t * Bb + b) * G4 + gidx] = v;
        }
    }
}

// ---------------- persistent LSTM chain: all 256 steps in one launch ----------------
// 128 CTAs (1/SM, all co-resident). 16-CTA batch-groups exchange fp16 h through L2 with a
// per-group software barrier. c in registers; B-hi in smem for the whole chain.
// Streamed tiles (h, B-lo) double-buffered via cp.async.cg (L1-bypass -> L2 coherent).
__global__ __launch_bounds__(128, 1)
void lstm_persist_kernel()
{
    extern __shared__ __align__(16) __half smp[];
    __half* sBHi = smp + P_SM_BHI;

    const int tid = threadIdx.x;
    const int warp = tid >> 5;
    const int lane = tid & 31;
    const int m_blk = blockIdx.x & 7;
    const int u_blk = blockIdx.x >> 3;
    const int m0 = m_blk * BM;
    const int u0 = u_blk * BU;
    const int r = lane >> 2;
    const int cb = (lane & 3) << 1;

    // ---- load persistent B-hi (h-part weights for this CTA's 128 gate rows) ----
    {
        int n = tid;
        int g = n >> 5, u = n & 31;
#pragma unroll
        for (int kcIdx = 0; kcIdx < NCHUNK; kcIdx++) {
            size_t off = (size_t)(g * Hh + u0 + u) * KTOT + Ff + kcIdx * KC;
            const uint4* wh = (const uint4*)&g_Whi[off];
            uint4* dh = (uint4*)&sBHi[kcIdx * CHUNK_ELEMS + n * KP];
#pragma unroll
            for (int q = 0; q < 4; q++) dh[q] = wh[q];
        }
    }

    float creg[16];
#pragma unroll
    for (int i = 0; i < 16; i++) creg[i] = 0.f;

    __syncthreads();

    for (int t = 0; t < Tt; t++) {
        const int src = t & 1;
        const int dst = src ^ 1;
        const __half* hsrc = g_h[src];

        auto issue = [&](int stage, int kc) {
            __half* st = smp + P_STAGE_BASE + stage * P_STAGE_ELEMS;
#pragma unroll
            for (int i = 0; i < 2; i++) {             // A (h): 64 rows x 32
                int c = tid + i * 128;
                int row = c >> 2, kq = (c & 3) << 3;
                size_t gi = (size_t)(m0 + row) * Hh + kc + kq;
                cp_async16(&st[P_OFF_A + row * KP + kq], &hsrc[gi]);
            }
#pragma unroll
            for (int i = 0; i < 4; i++) {             // B-lo: 128 rows x 32
                int c = tid + i * 128;
                int n = c >> 2, kq = (c & 3) << 3;
                int g = n >> 5, u = n & 31;
                size_t off = (size_t)(g * Hh + u0 + u) * KTOT + Ff + kc + kq;
                cp_async16(&st[P_OFF_BLO + n * KP + kq], &g_Wlo[off]);
            }
            cp_commit();
        };

        // accumulator init = precomputed x-part (+ biases, already folded)
        float acc[16][4];
#pragma unroll
        for (int nf = 0; nf < 16; nf++) {
            int g = nf >> 2, q = nf & 3;
            int gidx = g * Hh + u0 + q * 8 + cb;
#pragma unroll
            for (int rr = 0; rr < 2; rr++) {
                int b = m0 + warp * 16 + r + rr * 8;
                float2 v = *(const float2*)&g_xw[((size_t)t * Bb + b) * G4 + gidx];
                acc[nf][rr * 2] = v.x;
                acc[nf][rr * 2 + 1] = v.y;
            }
        }

        issue(0, 0);
        for (int kcIdx = 0; kcIdx < NCHUNK; kcIdx++) {
            int stage = kcIdx & 1;
            if (kcIdx + 1 < NCHUNK) { issue(stage ^ 1, (kcIdx + 1) * KC); cp_wait1(); }
            else cp_wait0();
            __syncthreads();
            __half* st = smp + P_STAGE_BASE + stage * P_STAGE_ELEMS;
            mma_chunk(st + P_OFF_A, &sBHi[kcIdx * CHUNK_ELEMS], st + P_OFF_BLO,
                      warp, lane, acc);
            __syncthreads();
        }

        // pointwise LSTM update; c in registers; h written as fp16
        __half* ho = g_h[dst];
#pragma unroll
        for (int q = 0; q < 4; q++) {
#pragma unroll
            for (int rr = 0; rr < 2; rr++) {
                int b = m0 + warp * 16 + r + rr * 8;
                float hv[2];
#pragma unroll
                for (int p = 0; p < 2; p++) {
                    int di = rr * 2 + p;
                    int ci = q * 4 + rr * 2 + p;
                    float pi = acc[q][di];
                    float pf = acc[4 + q][di];
                    float pg = acc[8 + q][di];
                    float po = acc[12 + q][di];
                    float ig = 1.f / (1.f + expf(-pi));
                    float fg = 1.f / (1.f + expf(-pf));
                    float gv = tanhf(pg);
                    float og = 1.f / (1.f + expf(-po));
                    float cv = fg * creg[ci] + ig * gv;
                    creg[ci] = cv;
                    hv[p] = og * tanhf(cv);
                }
                int u = u0 + q * 8 + cb;
                size_t oi = (size_t)b * Hh + u;
                *(__half2*)&ho[oi] = __floats2half2_rn(hv[0], hv[1]);
            }
        }

        // per-group software barrier (16 CTAs sharing m_blk)
        __syncthreads();
        if (tid == 0) {
            __threadfence();
            atomicAdd(&g_bar[m_blk], 1u);
            unsigned target = 16u * (unsigned)(t + 1);
            while (atomicAdd(&g_bar[m_blk], 0u) < target) { }
        }
        __syncthreads();
    }
}

// ---------------- output head: out[b] = h_T[b] . W_out + b_out ----------------
__global__ void head_kernel(const float* __restrict__ Wout, const float* __restrict__ bout,
                            float* __restrict__ out)
{
    int b = blockIdx.x * 4 + (threadIdx.x >> 5);
    int lane = threadIdx.x & 31;
    const __half* hrow = &g_h[0][(size_t)b * Hh];
    float s = 0.f;
#pragma unroll
    for (int u = lane; u < Hh; u += 32)
        s += __half2float(hrow[u]) * Wout[u];
#pragma unroll
    for (int o = 16; o; o >>= 1) s += __shfl_xor_sync(0xffffffffu, s, o);
    if (lane == 0) out[b] = s + bout[0];
}

extern "C" void kernel_launch(void* const* d_in, const int* in_sizes, int n_in,
                              void* d_out, int out_size)
{
    const float* x    = (const float*)d_in[0];
    const float* Wih  = (const float*)d_in[1];
    const float* Whh  = (const float*)d_in[2];
    const float* bih  = (const float*)d_in[3];
    const float* bhh  = (const float*)d_in[4];
    const float* Wout = (const float*)d_in[5];
    const float* bout = (const float*)d_in[6];
    float* out = (float*)d_out;

    static bool attr_set = false;
    if (!attr_set) {
        cudaFuncSetAttribute(lstm_persist_kernel,
                             cudaFuncAttributeMaxDynamicSharedMemorySize, SMEM_P_BYTES);
        cudaFuncSetAttribute(xw_kernel,
                             cudaFuncAttributeMaxDynamicSharedMemorySize, SMEM_X_BYTES);
        attr_set = true;
    }

    prep_kernel<<<512, 256>>>(x, Wih, Whh, bih, bhh);

    dim3 xgrid(Tt * (Bb / BM), Hh / BU);       // (2048, 16)
    xw_kernel<<<xgrid, 128, SMEM_X_BYTES>>>();

    lstm_persist_kernel<<<128, 128, SMEM_P_BYTES>>>();

    head_kernel<<<Bb / 4, 128>>>(Wout, bout, out);
}